// round 13
// baseline (speedup 1.0000x reference)
#include <cuda_runtime.h>
#include <stdint.h>

#define NN 16384
#define BB 64
#define TS 32768          // hash table slots (2x N, power of 2)
#define PREB 64           // blocks in pre kernel (one thread per node)
#define POSTB 64          // blocks in post kernel
#define PT 512            // threads per post block
#define K1B (NN / 8)      // 2048 blocks in heavy kernel

// ---------------- device scratch (static, no allocation) ----------------
__device__ __align__(16) unsigned int g_Kc[NN];    // per-column hash multiplier = f(x[j])
__device__ unsigned long long g_acc[NN];           // per-row neighbor-multiset hash
__device__ __align__(16) unsigned long long g_tab[TS]; // fused slot: key_hi50 | min node idx (0=empty)
__device__ int                g_rank[NN];          // in-block inclusive prefix of is_first
__device__ int                g_bsum[POSTB];       // per-block is_first totals
__device__ __align__(16) int  g_counts[BB * NN];   // per-graph color histogram (4 MB)
__device__ int                g_x64, g_b64;        // dtype flags: 1 if input is int64
__device__ unsigned int       g_barCnt[8];         // grid-barrier arrive counters
__device__ unsigned int       g_barGen[8];         // grid-barrier generations (monotonic)

__device__ __forceinline__ unsigned long long mix64(unsigned long long v) {
    v ^= v >> 33; v *= 0xFF51AFD7ED558CCDULL;
    v ^= v >> 33; v *= 0xC4CEB9FE1A85EC53ULL;
    v ^= v >> 33; return v;
}

__device__ __forceinline__ int load_small(const unsigned int* w, int i, int is64) {
    return (int)(is64 ? w[2 * i] : w[i]);
}

// Software grid barrier (sense via monotonic generation; replay-safe).
__device__ __forceinline__ void gridBarrier(int id, unsigned int nblocks) {
    __syncthreads();
    if (threadIdx.x == 0) {
        __threadfence();
        unsigned int gen = atomicAdd(&g_barGen[id], 0u);
        if (atomicAdd(&g_barCnt[id], 1u) == nblocks - 1u) {
            g_barCnt[id] = 0u;
            __threadfence();
            atomicAdd(&g_barGen[id], 1u);           // release
        } else {
            while (atomicAdd(&g_barGen[id], 0u) == gen) { }
        }
        __threadfence();
    }
    __syncthreads();
}

// ---------------- k_pre: per-block dtype detect + build Kc ----------------
__global__ __launch_bounds__(256) void k_pre(const unsigned int* __restrict__ xw,
                                             const unsigned int* __restrict__ bw) {
    __shared__ int sx[256];
    int t = threadIdx.x;
    int i = blockIdx.x * 256 + t;                    // node id (PREB*256 == NN)

    // x values < 16: odd words all-zero iff int64 (P[false pos] = 16^-512)
    int cx = (t < 512 && xw[2 * t + 1]) ? 1 : 0;
    sx[t] = cx;
    __syncthreads();
#pragma unroll
    for (int o = 128; o > 0; o >>= 1) { if (t < o) sx[t] += sx[t + o]; __syncthreads(); }
    int x64 = (sx[0] == 0) ? 1 : 0;

    if (blockIdx.x == 0) {
        int cb = (t < 512 && bw[2 * t + 1]) ? 1 : 0;
        sx[t] = cb;
        __syncthreads();
#pragma unroll
        for (int o = 128; o > 0; o >>= 1) { if (t < o) sx[t] += sx[t + o]; __syncthreads(); }
        if (t == 0) { g_b64 = (sx[0] == 0) ? 1 : 0; g_x64 = x64; }
    }

    int xv = load_small(xw, i, x64);
    g_Kc[i] = (unsigned int)(mix64(0x123456789ABCDEFULL +
                                   (unsigned long long)xv * 0x9E3779B97F4A7C15ULL) >> 16);
}

// ---------------- k1: heavy pass, warp-per-row + hidden scratch zeroing ----------------
__global__ __launch_bounds__(256) void k1_heavy(const float* __restrict__ adj) {
    int blk = blockIdx.x;
    int t = threadIdx.x;

    // hidden zeroing: counts (262144 int4 / 2048 blocks = 128/blk) + table (16 slots/blk)
    {
        int4* c4 = (int4*)g_counts;
        if (t < 128) c4[blk * 128 + t] = make_int4(0, 0, 0, 0);
        if (t >= 128 && t < 144) g_tab[blk * 16 + (t - 128)] = 0ULL;
    }

    int row  = blk * 8 + (t >> 5);
    int lane = t & 31;
    const uint4* __restrict__ arow = (const uint4*)(adj + (size_t)row * NN);
    const uint4* __restrict__ kt   = (const uint4*)g_Kc;

    unsigned long long a0 = 0, a1 = 0, a2 = 0, a3 = 0;
#pragma unroll 4
    for (int q = lane; q < 4096; q += 128) {
        uint4 u0 = __ldcs(arow + q);
        uint4 u1 = __ldcs(arow + q + 32);
        uint4 u2 = __ldcs(arow + q + 64);
        uint4 u3 = __ldcs(arow + q + 96);
        uint4 c0 = kt[q];
        uint4 c1 = kt[q + 32];
        uint4 c2 = kt[q + 64];
        uint4 c3 = kt[q + 96];
        a0 += (unsigned long long)u0.x * c0.x + (unsigned long long)u0.y * c0.y
            + (unsigned long long)u0.z * c0.z + (unsigned long long)u0.w * c0.w;
        a1 += (unsigned long long)u1.x * c1.x + (unsigned long long)u1.y * c1.y
            + (unsigned long long)u1.z * c1.z + (unsigned long long)u1.w * c1.w;
        a2 += (unsigned long long)u2.x * c2.x + (unsigned long long)u2.y * c2.y
            + (unsigned long long)u2.z * c2.z + (unsigned long long)u2.w * c2.w;
        a3 += (unsigned long long)u3.x * c3.x + (unsigned long long)u3.y * c3.y
            + (unsigned long long)u3.z * c3.z + (unsigned long long)u3.w * c3.w;
    }
    unsigned long long a = (a0 + a1) + (a2 + a3);
#pragma unroll
    for (int o = 16; o > 0; o >>= 1) a += __shfl_down_sync(0xffffffffu, a, o);
    if (lane == 0) g_acc[row] = a;
}

// ---------------- k_post: insert + lookup + rank + emit + norm (512 thr/block) ----------------
__global__ __launch_bounds__(PT) void k_post(const unsigned int* __restrict__ xw,
                                             const unsigned int* __restrict__ bw,
                                             const float* __restrict__ adj,
                                             float* __restrict__ out,
                                             long long out_size) {
    __shared__ int sScan[256];
    __shared__ int sOff[POSTB];
    int t = threadIdx.x;
    int blk = blockIdx.x;
    bool act = t < 256;                              // node-phase active threads
    int i = blk * 256 + t;                           // node id when act

    // ---- phase 1: key build + fused-slot hash insert (+lazy exact iso) ----
    unsigned long long hk = 0ULL;                    // high-50-bit key, top bit set (never 0)
    if (act) {
        unsigned long long acc = g_acc[i];
        bool iso = false;
        if (acc == 0ULL) {                           // w.p. ~2^-41 for non-isolated
            bool any = false;
            const float* rp = adj + (size_t)i * NN;
            for (int j = 0; j < NN && !any; j++) if (rp[j] != 0.0f) any = true;
            for (int r = 0; r < NN && !any; r++) if (adj[(size_t)r * NN + i] != 0.0f) any = true;
            iso = !any;
        }
        if (!iso) {
            int xv = load_small(xw, i, g_x64);
            unsigned long long h = mix64(acc + (unsigned long long)xv * 0xA24BAED4963EE407ULL);
            hk = (h | 0x8000000000000000ULL) & 0xFFFFFFFFFFFFC000ULL;
            unsigned long long val = hk | (unsigned long long)i;
            unsigned int s = (unsigned int)(h >> 32) & (TS - 1);
            for (;;) {
                unsigned long long prev = atomicCAS(&g_tab[s], 0ULL, val);
                if (prev == 0ULL) break;
                if ((prev & 0xFFFFFFFFFFFFC000ULL) == hk) { atomicMin(&g_tab[s], val); break; }
                s = (s + 1) & (TS - 1);
            }
        }
    }
    gridBarrier(1, POSTB);

    // ---- phase 2: lookup first-occurrence + block scan of is_first ----
    int f = -1;
    if (hk) {
        unsigned int s = (unsigned int)(hk >> 32) & (TS - 1);  // hk>>32 == h>>32 (mask clears low 14 bits)
        for (;;) {
            unsigned long long v = g_tab[s];
            if ((v & 0xFFFFFFFFFFFFC000ULL) == hk) { f = (int)(v & 0x3FFFULL); break; }
            s = (s + 1) & (TS - 1);
        }
    }
    int isf = (act && f == i) ? 1 : 0;
    if (act) sScan[t] = isf;
    __syncthreads();
#pragma unroll
    for (int o = 1; o < 256; o <<= 1) {
        int v = (act && t >= o) ? sScan[t - o] : 0;
        __syncthreads();
        if (act) sScan[t] += v;
        __syncthreads();
    }
    if (act) {
        int incl = sScan[t];                         // inclusive in-block prefix
        g_rank[i] = incl;
        if (t == 255) g_bsum[blk] = incl;
    }
    gridBarrier(2, POSTB);

    // ---- phase 3+4: reconstruct global rank + emit colors + histogram ----
    if (t == 0) {
        int run = 0;
#pragma unroll
        for (int b = 0; b < POSTB; b++) { sOff[b] = run; run += g_bsum[b]; }
    }
    __syncthreads();
    long long histElems = (long long)BB * NN;
    long long colorBase = (out_size >= histElems) ? histElems : 0;
    if (act) {
        int c = (f < 0) ? 0 : (g_rank[f] + sOff[f >> 8]);
        if (c > 0) {
            int g = load_small(bw, i, g_b64) & (BB - 1);
            atomicAdd(&g_counts[g * NN + (c - 1)], 1);
        }
        long long oi = colorBase + i;
        if (oi < out_size) out[oi] = (float)c;
    }
    gridBarrier(3, POSTB);                           // atomics visible before norm

    // ---- phase 5: per-graph L2 normalization, ALL 512 threads (coherent loads) ----
    {
        __shared__ double sred[PT];
        const int4* cnt4 = (const int4*)(g_counts + blk * NN);
        double ss = 0.0;
        for (int j = t; j < NN / 4; j += PT) {
            int4 v = cnt4[j];                        // plain coherent load (NOT __ldg)
            ss += (double)v.x * v.x + (double)v.y * v.y
                + (double)v.z * v.z + (double)v.w * v.w;
        }
        sred[t] = ss; __syncthreads();
#pragma unroll
        for (int o = PT / 2; o > 0; o >>= 1) { if (t < o) sred[t] += sred[t + o]; __syncthreads(); }
        double inv = 1.0 / sqrt(sred[0]);            // 0 -> inf -> NaN, matches reference
        if ((long long)(blk + 1) * NN <= out_size) {
            float4* o4 = (float4*)(out + (size_t)blk * NN);
            for (int j = t; j < NN / 4; j += PT) {
                int4 v = cnt4[j];
                float4 w;
                w.x = (float)((double)v.x * inv);
                w.y = (float)((double)v.y * inv);
                w.z = (float)((double)v.z * inv);
                w.w = (float)((double)v.w * inv);
                o4[j] = w;
            }
        }
    }
}

// ---------------- launcher ----------------
extern "C" void kernel_launch(void* const* d_in, const int* in_sizes, int n_in,
                              void* d_out, int out_size) {
    int iA = -1;
    for (int i = 0; i < n_in; i++)
        if ((long long)in_sizes[i] == (long long)NN * (long long)NN) iA = i;
    if (iA < 0) iA = (n_in > 1) ? 1 : 0;
    int ix = -1, ib = -1;
    for (int i = 0; i < n_in; i++) {
        if (i == iA) continue;
        if (ix < 0) ix = i; else if (ib < 0) ib = i;
    }
    if (ix < 0) ix = 0;
    if (ib < 0) ib = ix;

    const unsigned int* xw  = (const unsigned int*)d_in[ix];
    const float*        adj = (const float*)d_in[iA];
    const unsigned int* bw  = (const unsigned int*)d_in[ib];
    float* out = (float*)d_out;
    long long osz = (long long)out_size;

    k_pre<<<PREB, 256>>>(xw, bw);                    // idx 0
    k1_heavy<<<K1B, 256>>>(adj);                     // idx 1 (~170 us, DRAM-bound)
    k_post<<<POSTB, PT>>>(xw, bw, adj, out, osz);    // idx 2
}

// round 14
// speedup vs baseline: 1.2214x; 1.2214x over previous
#include <cuda_runtime.h>
#include <stdint.h>

#define NN 16384
#define BB 64
#define TS 32768          // hash table slots (2x N, power of 2)
#define PREB 64           // blocks in pre kernel (one thread per node)
#define POSTB 64          // blocks in post kernel
#define K1B (NN / 8)      // 2048 blocks in heavy kernel

// ---------------- device scratch (static, no allocation) ----------------
__device__ __align__(16) unsigned int g_Kc[NN];    // per-column hash multiplier = f(x[j])
__device__ unsigned long long g_acc[NN];           // per-row neighbor-multiset hash
__device__ __align__(16) unsigned long long g_tab[TS]; // fused slot: key_hi50 | min node idx (0=empty)
__device__ int                g_rank[NN];          // in-block inclusive prefix of is_first
__device__ int                g_bsum[POSTB];       // per-block is_first totals
__device__ __align__(16) int  g_counts[BB * NN];   // per-graph color histogram (4 MB)
__device__ __align__(16) int  g_norm2[BB];         // per-graph sum of count^2 (exact int)
__device__ int                g_x64, g_b64;        // dtype flags: 1 if input is int64
__device__ unsigned int       g_barCnt[8];         // grid-barrier arrive counters
__device__ unsigned int       g_barGen[8];         // grid-barrier generations (monotonic)

__device__ __forceinline__ unsigned long long mix64(unsigned long long v) {
    v ^= v >> 33; v *= 0xFF51AFD7ED558CCDULL;
    v ^= v >> 33; v *= 0xC4CEB9FE1A85EC53ULL;
    v ^= v >> 33; return v;
}

__device__ __forceinline__ int load_small(const unsigned int* w, int i, int is64) {
    return (int)(is64 ? w[2 * i] : w[i]);
}

// Software grid barrier (sense via monotonic generation; replay-safe).
__device__ __forceinline__ void gridBarrier(int id, unsigned int nblocks) {
    __syncthreads();
    if (threadIdx.x == 0) {
        __threadfence();
        unsigned int gen = atomicAdd(&g_barGen[id], 0u);
        if (atomicAdd(&g_barCnt[id], 1u) == nblocks - 1u) {
            g_barCnt[id] = 0u;
            __threadfence();
            atomicAdd(&g_barGen[id], 1u);           // release
        } else {
            while (atomicAdd(&g_barGen[id], 0u) == gen) { }
        }
        __threadfence();
    }
    __syncthreads();
}

// ---------------- k_pre: per-block dtype detect + build Kc ----------------
__global__ __launch_bounds__(256) void k_pre(const unsigned int* __restrict__ xw,
                                             const unsigned int* __restrict__ bw) {
    __shared__ int sx[256];
    int t = threadIdx.x;
    int i = blockIdx.x * 256 + t;                    // node id (PREB*256 == NN)

    // x values < 16: odd words all-zero iff int64 (P[false pos] = 16^-512)
    int cx = (t < 512 && xw[2 * t + 1]) ? 1 : 0;
    sx[t] = cx;
    __syncthreads();
#pragma unroll
    for (int o = 128; o > 0; o >>= 1) { if (t < o) sx[t] += sx[t + o]; __syncthreads(); }
    int x64 = (sx[0] == 0) ? 1 : 0;

    if (blockIdx.x == 0) {
        int cb = (t < 512 && bw[2 * t + 1]) ? 1 : 0;
        sx[t] = cb;
        __syncthreads();
#pragma unroll
        for (int o = 128; o > 0; o >>= 1) { if (t < o) sx[t] += sx[t + o]; __syncthreads(); }
        if (t == 0) { g_b64 = (sx[0] == 0) ? 1 : 0; g_x64 = x64; }
    }

    int xv = load_small(xw, i, x64);
    g_Kc[i] = (unsigned int)(mix64(0x123456789ABCDEFULL +
                                   (unsigned long long)xv * 0x9E3779B97F4A7C15ULL) >> 16);
}

// ---------------- k1: heavy pass, warp-per-row + hidden scratch zeroing ----------------
__global__ __launch_bounds__(256) void k1_heavy(const float* __restrict__ adj) {
    int blk = blockIdx.x;
    int t = threadIdx.x;

    // hidden zeroing: counts (262144 int4 / 2048 blocks = 128/blk) + table (16 slots/blk) + norm2
    {
        int4* c4 = (int4*)g_counts;
        if (t < 128) c4[blk * 128 + t] = make_int4(0, 0, 0, 0);
        if (t >= 128 && t < 144) g_tab[blk * 16 + (t - 128)] = 0ULL;
        if (blk == 0 && t >= 144 && t < 208) g_norm2[t - 144] = 0;
    }

    int row  = blk * 8 + (t >> 5);
    int lane = t & 31;
    const uint4* __restrict__ arow = (const uint4*)(adj + (size_t)row * NN);
    const uint4* __restrict__ kt   = (const uint4*)g_Kc;

    unsigned long long a0 = 0, a1 = 0, a2 = 0, a3 = 0;
#pragma unroll 4
    for (int q = lane; q < 4096; q += 128) {
        uint4 u0 = __ldcs(arow + q);
        uint4 u1 = __ldcs(arow + q + 32);
        uint4 u2 = __ldcs(arow + q + 64);
        uint4 u3 = __ldcs(arow + q + 96);
        uint4 c0 = kt[q];
        uint4 c1 = kt[q + 32];
        uint4 c2 = kt[q + 64];
        uint4 c3 = kt[q + 96];
        a0 += (unsigned long long)u0.x * c0.x + (unsigned long long)u0.y * c0.y
            + (unsigned long long)u0.z * c0.z + (unsigned long long)u0.w * c0.w;
        a1 += (unsigned long long)u1.x * c1.x + (unsigned long long)u1.y * c1.y
            + (unsigned long long)u1.z * c1.z + (unsigned long long)u1.w * c1.w;
        a2 += (unsigned long long)u2.x * c2.x + (unsigned long long)u2.y * c2.y
            + (unsigned long long)u2.z * c2.z + (unsigned long long)u2.w * c2.w;
        a3 += (unsigned long long)u3.x * c3.x + (unsigned long long)u3.y * c3.y
            + (unsigned long long)u3.z * c3.z + (unsigned long long)u3.w * c3.w;
    }
    unsigned long long a = (a0 + a1) + (a2 + a3);
#pragma unroll
    for (int o = 16; o > 0; o >>= 1) a += __shfl_down_sync(0xffffffffu, a, o);
    if (lane == 0) g_acc[row] = a;
}

// ---------------- k_post: insert(+zero-fill) + lookup/scan + emit + sparse norm ----------------
__global__ __launch_bounds__(256) void k_post(const unsigned int* __restrict__ xw,
                                              const unsigned int* __restrict__ bw,
                                              const float* __restrict__ adj,
                                              float* __restrict__ out,
                                              long long out_size) {
    __shared__ int sScan[256];
    __shared__ int sOff[POSTB];
    int t = threadIdx.x;
    int blk = blockIdx.x;
    int i = blk * 256 + t;                           // node id (POSTB*256 == NN)
    long long histElems = (long long)BB * NN;
    bool haveHist = (out_size >= histElems);
    long long colorBase = haveHist ? histElems : 0;

    // ---- phase 1: key build + fused-slot hash insert (+lazy exact iso) ----
    unsigned long long acc = g_acc[i];
    bool iso = false;
    if (acc == 0ULL) {                               // w.p. ~2^-41 for non-isolated
        bool any = false;
        const float* rp = adj + (size_t)i * NN;
        for (int j = 0; j < NN && !any; j++) if (rp[j] != 0.0f) any = true;
        for (int r = 0; r < NN && !any; r++) if (adj[(size_t)r * NN + i] != 0.0f) any = true;
        iso = !any;
    }
    unsigned long long hk = 0ULL;                    // high-50-bit key, top bit set (never 0)
    if (!iso) {
        int xv = load_small(xw, i, g_x64);
        unsigned long long h = mix64(acc + (unsigned long long)xv * 0xA24BAED4963EE407ULL);
        hk = (h | 0x8000000000000000ULL) & 0xFFFFFFFFFFFFC000ULL;
        unsigned long long val = hk | (unsigned long long)i;
        unsigned int s = (unsigned int)(h >> 32) & (TS - 1);
        for (;;) {
            unsigned long long prev = atomicCAS(&g_tab[s], 0ULL, val);
            if (prev == 0ULL) break;
            if ((prev & 0xFFFFFFFFFFFFC000ULL) == hk) { atomicMin(&g_tab[s], val); break; }
            s = (s + 1) & (TS - 1);
        }
    }
    // hidden zero-fill of the hist output region (4 MB / 64 blocks = 64 KB/block)
    if (haveHist) {
        float4 z = make_float4(0.f, 0.f, 0.f, 0.f);
        float4* o4 = (float4*)out;
        int base = blk * 4096;                       // 4096 float4 per block
#pragma unroll 4
        for (int j = t; j < 4096; j += 256) o4[base + j] = z;
    }
    gridBarrier(1, POSTB);

    // ---- phase 2: lookup first-occurrence + block scan of is_first ----
    int f = -1;
    if (hk) {
        unsigned int s = (unsigned int)(hk >> 32) & (TS - 1);  // hk>>32 == h>>32 (mask clears low 14 bits)
        for (;;) {
            unsigned long long v = g_tab[s];
            if ((v & 0xFFFFFFFFFFFFC000ULL) == hk) { f = (int)(v & 0x3FFFULL); break; }
            s = (s + 1) & (TS - 1);
        }
    }
    int isf = (f == i) ? 1 : 0;
    sScan[t] = isf;
    __syncthreads();
#pragma unroll
    for (int o = 1; o < 256; o <<= 1) {
        int v = (t >= o) ? sScan[t - o] : 0;
        __syncthreads();
        sScan[t] += v;
        __syncthreads();
    }
    int incl = sScan[t];                             // inclusive in-block prefix
    g_rank[i] = incl;
    if (t == 255) g_bsum[blk] = incl;
    gridBarrier(2, POSTB);

    // ---- phase 3+4: global rank + colors + histogram counts + incremental norm ----
    if (t == 0) {
        int run = 0;
#pragma unroll
        for (int b = 0; b < POSTB; b++) { sOff[b] = run; run += g_bsum[b]; }
    }
    __syncthreads();
    int c = (f < 0) ? 0 : (g_rank[f] + sOff[f >> 8]);
    int g = 0;
    if (c > 0) {
        g = load_small(bw, i, g_b64) & (BB - 1);
        int old = atomicAdd(&g_counts[g * NN + (c - 1)], 1);
        atomicAdd(&g_norm2[g], 2 * old + 1);         // sum count^2, incrementally exact
    }
    long long oi = colorBase + i;
    if (oi < out_size) out[oi] = (float)c;
    gridBarrier(3, POSTB);                           // counts + norm2 final

    // ---- phase 5: sparse normalize (scatter only touched cells) ----
    if (haveHist) {
        if (c > 0) {
            int v = g_counts[g * NN + (c - 1)];      // final count (coherent load)
            double norm = sqrt((double)g_norm2[g]);
            out[(size_t)g * NN + (c - 1)] = (float)((double)v / norm);
        }
        // rare exactness path: all-zero graph row -> reference 0/0 = NaN everywhere
        if (g_norm2[blk] == 0) {
            float nanv = __int_as_float(0x7FC00000);
            float4 n4 = make_float4(nanv, nanv, nanv, nanv);
            float4* o4 = (float4*)(out + (size_t)blk * NN);
            for (int j = t; j < NN / 4; j += 256) o4[j] = n4;
        }
    }
}

// ---------------- launcher ----------------
extern "C" void kernel_launch(void* const* d_in, const int* in_sizes, int n_in,
                              void* d_out, int out_size) {
    int iA = -1;
    for (int i = 0; i < n_in; i++)
        if ((long long)in_sizes[i] == (long long)NN * (long long)NN) iA = i;
    if (iA < 0) iA = (n_in > 1) ? 1 : 0;
    int ix = -1, ib = -1;
    for (int i = 0; i < n_in; i++) {
        if (i == iA) continue;
        if (ix < 0) ix = i; else if (ib < 0) ib = i;
    }
    if (ix < 0) ix = 0;
    if (ib < 0) ib = ix;

    const unsigned int* xw  = (const unsigned int*)d_in[ix];
    const float*        adj = (const float*)d_in[iA];
    const unsigned int* bw  = (const unsigned int*)d_in[ib];
    float* out = (float*)d_out;
    long long osz = (long long)out_size;

    k_pre<<<PREB, 256>>>(xw, bw);                    // idx 0
    k1_heavy<<<K1B, 256>>>(adj);                     // idx 1 (~170 us, DRAM-bound)
    k_post<<<POSTB, 256>>>(xw, bw, adj, out, osz);   // idx 2
}

// round 16
// speedup vs baseline: 1.2704x; 1.0401x over previous
#include <cuda_runtime.h>
#include <stdint.h>

#define NN 16384
#define BB 64
#define TS 32768          // hash table slots (2x N, power of 2)
#define PREB 64           // blocks in pre kernel (one thread per node)
#define POSTB 64          // blocks in post kernel
#define K1B (NN / 8)      // 2048 blocks in heavy kernel

// ---------------- device scratch (static, no allocation) ----------------
__device__ __align__(16) unsigned int g_Kc[NN];    // per-column hash multiplier = f(x[j])
__device__ unsigned long long g_key[NN];           // per-node signature key hk (0 = isolated)
__device__ __align__(16) unsigned long long g_tab[TS]; // fused slot: key_hi50 | min node idx (0=empty)
__device__ int                g_rank[NN];          // in-block inclusive prefix of is_first
__device__ int                g_bsum[POSTB];       // per-block is_first totals
__device__ __align__(16) int  g_counts[BB * NN];   // per-graph color histogram (4 MB)
__device__ __align__(16) int  g_norm2[BB];         // per-graph sum of count^2 (exact int)
__device__ int                g_x64, g_b64;        // dtype flags: 1 if input is int64
__device__ unsigned int       g_barCnt[8];         // grid-barrier arrive counters
__device__ unsigned int       g_barGen[8];         // grid-barrier generations (monotonic)

__device__ __forceinline__ unsigned long long mix64(unsigned long long v) {
    v ^= v >> 33; v *= 0xFF51AFD7ED558CCDULL;
    v ^= v >> 33; v *= 0xC4CEB9FE1A85EC53ULL;
    v ^= v >> 33; return v;
}

__device__ __forceinline__ int load_small(const unsigned int* w, int i, int is64) {
    return (int)(is64 ? w[2 * i] : w[i]);
}

// Software grid barrier (sense via monotonic generation; replay-safe).
__device__ __forceinline__ void gridBarrier(int id, unsigned int nblocks) {
    __syncthreads();
    if (threadIdx.x == 0) {
        __threadfence();
        unsigned int gen = atomicAdd(&g_barGen[id], 0u);
        if (atomicAdd(&g_barCnt[id], 1u) == nblocks - 1u) {
            g_barCnt[id] = 0u;
            __threadfence();
            atomicAdd(&g_barGen[id], 1u);           // release
        } else {
            while (atomicAdd(&g_barGen[id], 0u) == gen) { }
        }
        __threadfence();
    }
    __syncthreads();
}

// ---------------- k_pre: dtype detect + build Kc + zero hash table ----------------
// Table zeroing MUST complete before k1's tail inserts -> it lives here (kernel
// boundary is the fence). counts/out-hist/norm2 zeroing stays in k1 (only k_post
// writes those -- no race).
__global__ __launch_bounds__(256) void k_pre(const unsigned int* __restrict__ xw,
                                             const unsigned int* __restrict__ bw) {
    __shared__ int sx[256];
    int t = threadIdx.x;
    int i = blockIdx.x * 256 + t;                    // node id (PREB*256 == NN)

    // zero 2 table slots per thread (16384 threads x 2 = 32768 slots)
    g_tab[2 * i]     = 0ULL;
    g_tab[2 * i + 1] = 0ULL;

    // x values < 16: odd words all-zero iff int64 (P[false pos] = 16^-512)
    int cx = (t < 512 && xw[2 * t + 1]) ? 1 : 0;
    sx[t] = cx;
    __syncthreads();
#pragma unroll
    for (int o = 128; o > 0; o >>= 1) { if (t < o) sx[t] += sx[t + o]; __syncthreads(); }
    int x64 = (sx[0] == 0) ? 1 : 0;

    if (blockIdx.x == 0) {
        int cb = (t < 512 && bw[2 * t + 1]) ? 1 : 0;
        sx[t] = cb;
        __syncthreads();
#pragma unroll
        for (int o = 128; o > 0; o >>= 1) { if (t < o) sx[t] += sx[t + o]; __syncthreads(); }
        if (t == 0) { g_b64 = (sx[0] == 0) ? 1 : 0; g_x64 = x64; }
    }

    int xv = load_small(xw, i, x64);
    g_Kc[i] = (unsigned int)(mix64(0x123456789ABCDEFULL +
                                   (unsigned long long)xv * 0x9E3779B97F4A7C15ULL) >> 16);
}

// ---------------- k1: heavy pass + hidden zeroing + tail hash-table insert ----------------
__global__ __launch_bounds__(256) void k1_heavy(const float* __restrict__ adj,
                                                const unsigned int* __restrict__ xw,
                                                float* __restrict__ out,
                                                int haveHist) {
    int blk = blockIdx.x;
    int t = threadIdx.x;

    // hidden zeroing of k_post-only scratch: counts (128 int4/blk),
    // out-hist (128 float4/blk), norm2 (block 0). NO table zeroing here (race!).
    {
        int4* c4 = (int4*)g_counts;
        if (t < 128) c4[blk * 128 + t] = make_int4(0, 0, 0, 0);
        if (haveHist && t >= 128 && t < 256) {
            float4* o4 = (float4*)out;
            o4[blk * 128 + (t - 128)] = make_float4(0.f, 0.f, 0.f, 0.f);
        }
        if (blk == 0 && t < 64) g_norm2[t] = 0;
    }

    int row  = blk * 8 + (t >> 5);
    int lane = t & 31;
    const uint4* __restrict__ arow = (const uint4*)(adj + (size_t)row * NN);
    const uint4* __restrict__ kt   = (const uint4*)g_Kc;

    unsigned long long a0 = 0, a1 = 0, a2 = 0, a3 = 0;
#pragma unroll 4
    for (int q = lane; q < 4096; q += 128) {
        uint4 u0 = __ldcs(arow + q);
        uint4 u1 = __ldcs(arow + q + 32);
        uint4 u2 = __ldcs(arow + q + 64);
        uint4 u3 = __ldcs(arow + q + 96);
        uint4 c0 = kt[q];
        uint4 c1 = kt[q + 32];
        uint4 c2 = kt[q + 64];
        uint4 c3 = kt[q + 96];
        a0 += (unsigned long long)u0.x * c0.x + (unsigned long long)u0.y * c0.y
            + (unsigned long long)u0.z * c0.z + (unsigned long long)u0.w * c0.w;
        a1 += (unsigned long long)u1.x * c1.x + (unsigned long long)u1.y * c1.y
            + (unsigned long long)u1.z * c1.z + (unsigned long long)u1.w * c1.w;
        a2 += (unsigned long long)u2.x * c2.x + (unsigned long long)u2.y * c2.y
            + (unsigned long long)u2.z * c2.z + (unsigned long long)u2.w * c2.w;
        a3 += (unsigned long long)u3.x * c3.x + (unsigned long long)u3.y * c3.y
            + (unsigned long long)u3.z * c3.z + (unsigned long long)u3.w * c3.w;
    }
    unsigned long long a = (a0 + a1) + (a2 + a3);
#pragma unroll
    for (int o = 16; o > 0; o >>= 1) a += __shfl_down_sync(0xffffffffu, a, o);

    // tail: lane 0 of each warp inserts its row into the hash table
    if (lane == 0) {
        unsigned long long acc = a;
        bool iso = false;
        if (acc == 0ULL) {                           // w.p. ~2^-41 for non-isolated: exact check
            bool any = false;
            const float* rp = adj + (size_t)row * NN;
            for (int j = 0; j < NN && !any; j++) if (rp[j] != 0.0f) any = true;
            for (int r = 0; r < NN && !any; r++) if (adj[(size_t)r * NN + row] != 0.0f) any = true;
            iso = !any;
        }
        unsigned long long hk = 0ULL;                // high-50-bit key, top bit set (never 0)
        if (!iso) {
            int xv = load_small(xw, row, g_x64);
            unsigned long long h = mix64(acc + (unsigned long long)xv * 0xA24BAED4963EE407ULL);
            hk = (h | 0x8000000000000000ULL) & 0xFFFFFFFFFFFFC000ULL;
            unsigned long long val = hk | (unsigned long long)row;
            unsigned int s = (unsigned int)(h >> 32) & (TS - 1);
            for (int p = 0; p < TS; p++) {           // bounded probe (defensive)
                unsigned long long prev = atomicCAS(&g_tab[s], 0ULL, val);
                if (prev == 0ULL) break;
                if ((prev & 0xFFFFFFFFFFFFC000ULL) == hk) { atomicMin(&g_tab[s], val); break; }
                s = (s + 1) & (TS - 1);
            }
        }
        g_key[row] = hk;
    }
}

// ---------------- k_post: lookup/scan + emit + sparse norm (2 grid barriers) ----------------
__global__ __launch_bounds__(256) void k_post(const unsigned int* __restrict__ bw,
                                              float* __restrict__ out,
                                              long long out_size) {
    __shared__ int sScan[256];
    __shared__ int sOff[POSTB];
    int t = threadIdx.x;
    int blk = blockIdx.x;
    int i = blk * 256 + t;                           // node id (POSTB*256 == NN)
    long long histElems = (long long)BB * NN;
    bool haveHist = (out_size >= histElems);
    long long colorBase = haveHist ? histElems : 0;

    // ---- phase A: lookup first-occurrence + block scan of is_first ----
    unsigned long long hk = g_key[i];
    int f = -1;
    if (hk) {
        unsigned int s = (unsigned int)(hk >> 32) & (TS - 1);  // hk>>32 == h>>32 (mask clears low 14 bits)
        for (int p = 0; p < TS; p++) {               // bounded probe (defensive)
            unsigned long long v = g_tab[s];
            if ((v & 0xFFFFFFFFFFFFC000ULL) == hk) { f = (int)(v & 0x3FFFULL); break; }
            s = (s + 1) & (TS - 1);
        }
    }
    int isf = (f == i) ? 1 : 0;
    sScan[t] = isf;
    __syncthreads();
#pragma unroll
    for (int o = 1; o < 256; o <<= 1) {
        int v = (t >= o) ? sScan[t - o] : 0;
        __syncthreads();
        sScan[t] += v;
        __syncthreads();
    }
    int incl = sScan[t];                             // inclusive in-block prefix
    g_rank[i] = incl;
    if (t == 255) g_bsum[blk] = incl;
    gridBarrier(1, POSTB);

    // ---- phase B: global rank + colors + histogram counts + incremental norm ----
    if (t == 0) {
        int run = 0;
#pragma unroll
        for (int b = 0; b < POSTB; b++) { sOff[b] = run; run += g_bsum[b]; }
    }
    __syncthreads();
    int c = (f < 0) ? 0 : (g_rank[f] + sOff[f >> 8]);
    int g = 0;
    if (c > 0) {
        g = load_small(bw, i, g_b64) & (BB - 1);
        int old = atomicAdd(&g_counts[g * NN + (c - 1)], 1);
        atomicAdd(&g_norm2[g], 2 * old + 1);         // sum count^2, incrementally exact
    }
    long long oi = colorBase + i;
    if (oi < out_size) out[oi] = (float)c;
    gridBarrier(2, POSTB);                           // counts + norm2 final

    // ---- phase C: sparse normalize (scatter only touched cells) ----
    if (haveHist) {
        if (c > 0) {
            int v = g_counts[g * NN + (c - 1)];      // final count (coherent load)
            double norm = sqrt((double)g_norm2[g]);
            out[(size_t)g * NN + (c - 1)] = (float)((double)v / norm);
        }
        // rare exactness path: all-zero graph row -> reference 0/0 = NaN everywhere
        if (g_norm2[blk] == 0) {
            float nanv = __int_as_float(0x7FC00000);
            float4 n4 = make_float4(nanv, nanv, nanv, nanv);
            float4* o4 = (float4*)(out + (size_t)blk * NN);
            for (int j = t; j < NN / 4; j += 256) o4[j] = n4;
        }
    }
}

// ---------------- launcher ----------------
extern "C" void kernel_launch(void* const* d_in, const int* in_sizes, int n_in,
                              void* d_out, int out_size) {
    int iA = -1;
    for (int i = 0; i < n_in; i++)
        if ((long long)in_sizes[i] == (long long)NN * (long long)NN) iA = i;
    if (iA < 0) iA = (n_in > 1) ? 1 : 0;
    int ix = -1, ib = -1;
    for (int i = 0; i < n_in; i++) {
        if (i == iA) continue;
        if (ix < 0) ix = i; else if (ib < 0) ib = i;
    }
    if (ix < 0) ix = 0;
    if (ib < 0) ib = ix;

    const unsigned int* xw  = (const unsigned int*)d_in[ix];
    const float*        adj = (const float*)d_in[iA];
    const unsigned int* bw  = (const unsigned int*)d_in[ib];
    float* out = (float*)d_out;
    long long osz = (long long)out_size;
    int haveHist = (osz >= (long long)BB * NN) ? 1 : 0;

    k_pre<<<PREB, 256>>>(xw, bw);                    // idx 0 (zeroes table BEFORE k1 inserts)
    k1_heavy<<<K1B, 256>>>(adj, xw, out, haveHist);  // idx 1 (~170 us + hidden insert tail)
    k_post<<<POSTB, 256>>>(bw, out, osz);            // idx 2
}